// round 1
// baseline (speedup 1.0000x reference)
#include <cuda_runtime.h>
#include <math.h>

#define T_TOK 4096
#define DIM   1024
#define HID   4096
#define NE    8

#define BM 128
#define BN 128
#define BK 16
// worst-case padded slots: 8192 pairs + 8 experts * (BM-1) padding, rounded to 72*128
#define MAX_SLOTS 9216

// ---------------- device scratch (static, no runtime alloc) ----------------
__device__ int   g_cnt[NE];
__device__ int   g_cursor[NE];
__device__ int   g_off[NE];
__device__ int   g_padded_total;
__device__ int   g_sel[T_TOK][2];
__device__ float g_wts[T_TOK][2];
__device__ int   g_slot_tok[MAX_SLOTS];
__device__ int   g_slot_e[MAX_SLOTS];
__device__ float g_slot_w[MAX_SLOTS];
__device__ float g_H[(size_t)MAX_SLOTS * HID];   // ~151 MB intermediate activations

// ---------------- kernel 0: zero output + control ----------------
__global__ void init_kernel(float* out, int n) {
    int i = blockIdx.x * blockDim.x + threadIdx.x;
    if (i < NE)            g_cnt[i] = 0;
    else if (i < 2 * NE)   g_cursor[i - NE] = 0;
    for (int j = i; j < n; j += gridDim.x * blockDim.x) out[j] = 0.0f;
}

// ---------------- kernel 1: routing (1 warp per token) ----------------
__global__ void route_kernel(const float* __restrict__ x,
                             const float* __restrict__ Wr,
                             const float* __restrict__ br) {
    int warp = (blockIdx.x * blockDim.x + threadIdx.x) >> 5;
    int lane = threadIdx.x & 31;
    if (warp >= T_TOK) return;
    const float* xr = x + (size_t)warp * DIM;

    float acc[NE];
#pragma unroll
    for (int e = 0; e < NE; e++) acc[e] = 0.0f;

    for (int k = lane; k < DIM; k += 32) {
        float xv = __ldg(xr + k);
        const float4* w4 = (const float4*)(Wr + (size_t)k * NE);
        float4 wa = __ldg(w4);
        float4 wb = __ldg(w4 + 1);
        acc[0] += xv * wa.x; acc[1] += xv * wa.y;
        acc[2] += xv * wa.z; acc[3] += xv * wa.w;
        acc[4] += xv * wb.x; acc[5] += xv * wb.y;
        acc[6] += xv * wb.z; acc[7] += xv * wb.w;
    }
#pragma unroll
    for (int e = 0; e < NE; e++)
#pragma unroll
        for (int o = 16; o > 0; o >>= 1)
            acc[e] += __shfl_down_sync(0xFFFFFFFFu, acc[e], o);

    if (lane == 0) {
        float l[NE];
#pragma unroll
        for (int e = 0; e < NE; e++) l[e] = acc[e] + br[e];
        int i0 = 0;
#pragma unroll
        for (int e = 1; e < NE; e++) if (l[e] > l[i0]) i0 = e;
        int i1 = (i0 == 0) ? 1 : 0;
#pragma unroll
        for (int e = 0; e < NE; e++) if (e != i0 && l[e] > l[i1]) i1 = e;
        // softmax over the two selected logits (l[i0] >= l[i1])
        float w0 = 1.0f / (1.0f + expf(l[i1] - l[i0]));
        g_sel[warp][0] = i0; g_sel[warp][1] = i1;
        g_wts[warp][0] = w0; g_wts[warp][1] = 1.0f - w0;
        atomicAdd(&g_cnt[i0], 1);
        atomicAdd(&g_cnt[i1], 1);
    }
}

// ---------------- kernel 2: per-expert padded offsets + slot init ----------------
__global__ void offsets_kernel() {
    __shared__ int soff[NE + 1];
    if (threadIdx.x == 0) {
        int tot = 0;
        for (int e = 0; e < NE; e++) {
            g_off[e] = tot;
            soff[e]  = tot;
            int padded = ((g_cnt[e] + BM - 1) / BM) * BM;
            tot += padded;
        }
        soff[NE] = tot;
        g_padded_total = tot;
    }
    __syncthreads();
    int tot = soff[NE];
    for (int s = threadIdx.x; s < tot; s += blockDim.x) {
        int e = 0;
        while (s >= soff[e + 1]) e++;
        g_slot_e[s]   = e;
        g_slot_tok[s] = -1;
    }
}

// ---------------- kernel 3: scatter (token, expert) pairs to slots ----------------
__global__ void scatter_kernel() {
    int t = blockIdx.x * blockDim.x + threadIdx.x;
    if (t >= T_TOK) return;
#pragma unroll
    for (int j = 0; j < 2; j++) {
        int e   = g_sel[t][j];
        int pos = atomicAdd(&g_cursor[e], 1);
        int s   = g_off[e] + pos;
        g_slot_tok[s] = t;
        g_slot_w[s]   = g_wts[t][j];
    }
}

// ---------------- kernel 4: GEMM1 (X @ W1_e + b1) + exact GELU -> g_H ----------------
__global__ __launch_bounds__(256) void gemm1_kernel(const float* __restrict__ X,
                                                    const float* __restrict__ W1,
                                                    const float* __restrict__ b1) {
    const int m0 = blockIdx.x * BM;
    if (m0 >= g_padded_total) return;
    const int n0 = blockIdx.y * BN;
    const int e  = g_slot_e[m0];
    const float* Bp = W1 + (size_t)e * DIM * HID;   // [1024, 4096] row-major

    __shared__ float As[BK][BM];
    __shared__ float Bs[BK][BN];

    const int tid = threadIdx.x;
    const int ty  = tid >> 4;   // 0..15
    const int tx  = tid & 15;   // 0..15

    // A load map: 2 float4 per thread per k-step (gathered token rows)
    int arow[2], ak[2];
    const float* aptr[2];
#pragma unroll
    for (int i = 0; i < 2; i++) {
        int idx = tid + 256 * i;
        arow[i] = idx >> 2;
        ak[i]   = (idx & 3) << 2;
        int tok = g_slot_tok[m0 + arow[i]];
        aptr[i] = (tok >= 0) ? (X + (size_t)tok * DIM + ak[i]) : (const float*)0;
    }
    // B load map
    int bk[2], bn[2];
#pragma unroll
    for (int i = 0; i < 2; i++) {
        int idx = tid + 256 * i;
        bk[i] = idx >> 5;
        bn[i] = (idx & 31) << 2;
    }

    float acc[8][8];
#pragma unroll
    for (int i = 0; i < 8; i++)
#pragma unroll
        for (int j = 0; j < 8; j++) acc[i][j] = 0.0f;

    for (int k0 = 0; k0 < DIM; k0 += BK) {
#pragma unroll
        for (int i = 0; i < 2; i++) {
            float4 v = aptr[i] ? *(const float4*)(aptr[i] + k0) : make_float4(0.f, 0.f, 0.f, 0.f);
            As[ak[i] + 0][arow[i]] = v.x;
            As[ak[i] + 1][arow[i]] = v.y;
            As[ak[i] + 2][arow[i]] = v.z;
            As[ak[i] + 3][arow[i]] = v.w;
        }
#pragma unroll
        for (int i = 0; i < 2; i++) {
            float4 v = *(const float4*)(Bp + (size_t)(k0 + bk[i]) * HID + n0 + bn[i]);
            *(float4*)(&Bs[bk[i]][bn[i]]) = v;
        }
        __syncthreads();
#pragma unroll
        for (int kk = 0; kk < BK; kk++) {
            float a[8], b[8];
            *(float4*)(&a[0]) = *(const float4*)(&As[kk][ty * 4]);
            *(float4*)(&a[4]) = *(const float4*)(&As[kk][64 + ty * 4]);
            *(float4*)(&b[0]) = *(const float4*)(&Bs[kk][tx * 4]);
            *(float4*)(&b[4]) = *(const float4*)(&Bs[kk][64 + tx * 4]);
#pragma unroll
            for (int i = 0; i < 8; i++)
#pragma unroll
                for (int j = 0; j < 8; j++) acc[i][j] += a[i] * b[j];
        }
        __syncthreads();
    }

    // epilogue: + b1, exact GELU, store to H
#pragma unroll
    for (int i = 0; i < 8; i++) {
        int rr = (i < 4) ? (ty * 4 + i) : (64 + ty * 4 + (i - 4));
        size_t hbase = (size_t)(m0 + rr) * HID + n0;
#pragma unroll
        for (int j = 0; j < 8; j++) {
            int cc = (j < 4) ? (tx * 4 + j) : (64 + tx * 4 + (j - 4));
            float h = acc[i][j] + __ldg(&b1[(size_t)e * HID + n0 + cc]);
            h = 0.5f * h * (1.0f + erff(h * 0.70710678118654752f));
            g_H[hbase + cc] = h;
        }
    }
}

// ---------------- kernel 5: GEMM2 (H @ W2_e + b2), weighted scatter to out ----------------
__global__ __launch_bounds__(256) void gemm2_kernel(const float* __restrict__ W2,
                                                    const float* __restrict__ b2,
                                                    float* __restrict__ out) {
    const int m0 = blockIdx.x * BM;
    if (m0 >= g_padded_total) return;
    const int n0 = blockIdx.y * BN;
    const int e  = g_slot_e[m0];
    const float* Bp = W2 + (size_t)e * HID * DIM;   // [4096, 1024] row-major

    __shared__ float As[BK][BM];
    __shared__ float Bs[BK][BN];

    const int tid = threadIdx.x;
    const int ty  = tid >> 4;
    const int tx  = tid & 15;

    int arow[2], ak[2];
#pragma unroll
    for (int i = 0; i < 2; i++) {
        int idx = tid + 256 * i;
        arow[i] = idx >> 2;
        ak[i]   = (idx & 3) << 2;
    }
    int bk[2], bn[2];
#pragma unroll
    for (int i = 0; i < 2; i++) {
        int idx = tid + 256 * i;
        bk[i] = idx >> 5;
        bn[i] = (idx & 31) << 2;
    }

    float acc[8][8];
#pragma unroll
    for (int i = 0; i < 8; i++)
#pragma unroll
        for (int j = 0; j < 8; j++) acc[i][j] = 0.0f;

    for (int k0 = 0; k0 < HID; k0 += BK) {
#pragma unroll
        for (int i = 0; i < 2; i++) {
            float4 v = *(const float4*)(g_H + (size_t)(m0 + arow[i]) * HID + k0 + ak[i]);
            As[ak[i] + 0][arow[i]] = v.x;
            As[ak[i] + 1][arow[i]] = v.y;
            As[ak[i] + 2][arow[i]] = v.z;
            As[ak[i] + 3][arow[i]] = v.w;
        }
#pragma unroll
        for (int i = 0; i < 2; i++) {
            float4 v = *(const float4*)(Bp + (size_t)(k0 + bk[i]) * DIM + n0 + bn[i]);
            *(float4*)(&Bs[bk[i]][bn[i]]) = v;
        }
        __syncthreads();
#pragma unroll
        for (int kk = 0; kk < BK; kk++) {
            float a[8], b[8];
            *(float4*)(&a[0]) = *(const float4*)(&As[kk][ty * 4]);
            *(float4*)(&a[4]) = *(const float4*)(&As[kk][64 + ty * 4]);
            *(float4*)(&b[0]) = *(const float4*)(&Bs[kk][tx * 4]);
            *(float4*)(&b[4]) = *(const float4*)(&Bs[kk][64 + tx * 4]);
#pragma unroll
            for (int i = 0; i < 8; i++)
#pragma unroll
                for (int j = 0; j < 8; j++) acc[i][j] += a[i] * b[j];
        }
        __syncthreads();
    }

    // epilogue: + b2, weight, atomic combine into out
#pragma unroll
    for (int i = 0; i < 8; i++) {
        int rr  = (i < 4) ? (ty * 4 + i) : (64 + ty * 4 + (i - 4));
        int m   = m0 + rr;
        int tok = g_slot_tok[m];
        if (tok < 0) continue;
        float w = g_slot_w[m];
        float* orow = out + (size_t)tok * DIM;
#pragma unroll
        for (int j = 0; j < 8; j++) {
            int cc  = (j < 4) ? (tx * 4 + j) : (64 + tx * 4 + (j - 4));
            int n   = n0 + cc;
            float y = acc[i][j] + __ldg(&b2[(size_t)e * DIM + n]);
            atomicAdd(&orow[n], w * y);
        }
    }
}

// ---------------- launch ----------------
extern "C" void kernel_launch(void* const* d_in, const int* in_sizes, int n_in,
                              void* d_out, int out_size) {
    const float* x  = (const float*)d_in[0];
    const float* Wr = (const float*)d_in[1];
    const float* br = (const float*)d_in[2];
    const float* W1 = (const float*)d_in[3];
    const float* b1 = (const float*)d_in[4];
    const float* W2 = (const float*)d_in[5];
    const float* b2 = (const float*)d_in[6];
    float* out = (float*)d_out;

    init_kernel<<<1024, 256>>>(out, out_size);
    route_kernel<<<T_TOK / 4, 128>>>(x, Wr, br);
    offsets_kernel<<<1, 256>>>();
    scatter_kernel<<<T_TOK / 256, 256>>>();

    dim3 g1(MAX_SLOTS / BM, HID / BN);   // 72 x 32
    gemm1_kernel<<<g1, 256>>>(x, W1, b1);

    dim3 g2(MAX_SLOTS / BM, DIM / BN);   // 72 x 8
    gemm2_kernel<<<g2, 256>>>(W2, b2, out);
}

// round 3
// speedup vs baseline: 5.1280x; 5.1280x over previous
#include <cuda_runtime.h>
#include <cuda_fp16.h>
#include <math.h>
#include <stdint.h>

#define T_TOK 4096
#define DIM   1024
#define HID   4096
#define NE    8

#define BM 128
#define BN 128
#define MAX_SLOTS 9216        // 8192 pairs + worst-case per-expert padding, 72 tiles
#define MTILES (MAX_SLOTS/BM)

// ---------------- device scratch (static) ----------------
__device__ int   g_cnt[NE];
__device__ int   g_cursor[NE];
__device__ int   g_off[NE];
__device__ int   g_padded_total;
__device__ int   g_sel[T_TOK][2];
__device__ float g_wts[T_TOK][2];
__device__ int   g_slot_tok[MAX_SLOTS];
__device__ int   g_slot_e[MAX_SLOTS];
__device__ float g_slot_w[MAX_SLOTS];
__device__ int   g_tok_slot[T_TOK][2];

__device__ __align__(256) __half g_Xf[MAX_SLOTS * DIM];
__device__ __align__(256) __half g_W1f[(size_t)NE * DIM * HID];
__device__ __align__(256) __half g_W2f[(size_t)NE * HID * DIM];
__device__ __align__(256) __half g_Hf[(size_t)MAX_SLOTS * HID];
__device__ __align__(256) float  g_Y[(size_t)MAX_SLOTS * DIM];

// ---------------- helpers ----------------
__device__ __forceinline__ uint32_t smem_u32(const void* p) {
    uint32_t a;
    asm("{ .reg .u64 t; cvta.to.shared.u64 t, %1; cvt.u32.u64 %0, t; }" : "=r"(a) : "l"(p));
    return a;
}
__device__ __forceinline__ void cp16(uint32_t dst, const void* src) {
    asm volatile("cp.async.cg.shared.global [%0], [%1], 16;" :: "r"(dst), "l"(src) : "memory");
}
__device__ __forceinline__ void ldm_x4(uint32_t* r, uint32_t addr) {
    asm volatile("ldmatrix.sync.aligned.m8n8.x4.shared.b16 {%0,%1,%2,%3}, [%4];"
                 : "=r"(r[0]), "=r"(r[1]), "=r"(r[2]), "=r"(r[3]) : "r"(addr));
}
__device__ __forceinline__ void ldm_x4_t(uint32_t* r, uint32_t addr) {
    asm volatile("ldmatrix.sync.aligned.m8n8.x4.trans.shared.b16 {%0,%1,%2,%3}, [%4];"
                 : "=r"(r[0]), "=r"(r[1]), "=r"(r[2]), "=r"(r[3]) : "r"(addr));
}
__device__ __forceinline__ void mma16816(float* d, const uint32_t* a, uint32_t b0, uint32_t b1) {
    asm volatile("mma.sync.aligned.m16n8k16.row.col.f32.f16.f16.f32 "
                 "{%0,%1,%2,%3}, {%4,%5,%6,%7}, {%8,%9}, {%0,%1,%2,%3};"
                 : "+f"(d[0]), "+f"(d[1]), "+f"(d[2]), "+f"(d[3])
                 : "r"(a[0]), "r"(a[1]), "r"(a[2]), "r"(a[3]), "r"(b0), "r"(b1));
}

// ---------------- prep kernels ----------------
__global__ void init_kernel() {
    int i = threadIdx.x;
    if (i < NE) { g_cnt[i] = 0; g_cursor[i] = 0; }
}

__global__ void route_kernel(const float* __restrict__ x,
                             const float* __restrict__ Wr,
                             const float* __restrict__ br) {
    int warp = (blockIdx.x * blockDim.x + threadIdx.x) >> 5;
    int lane = threadIdx.x & 31;
    if (warp >= T_TOK) return;
    const float* xr = x + (size_t)warp * DIM;
    float acc[NE];
#pragma unroll
    for (int e = 0; e < NE; e++) acc[e] = 0.0f;
    for (int k = lane; k < DIM; k += 32) {
        float xv = __ldg(xr + k);
        const float4* w4 = (const float4*)(Wr + (size_t)k * NE);
        float4 wa = __ldg(w4), wb = __ldg(w4 + 1);
        acc[0] += xv * wa.x; acc[1] += xv * wa.y; acc[2] += xv * wa.z; acc[3] += xv * wa.w;
        acc[4] += xv * wb.x; acc[5] += xv * wb.y; acc[6] += xv * wb.z; acc[7] += xv * wb.w;
    }
#pragma unroll
    for (int e = 0; e < NE; e++)
#pragma unroll
        for (int o = 16; o > 0; o >>= 1)
            acc[e] += __shfl_down_sync(0xFFFFFFFFu, acc[e], o);
    if (lane == 0) {
        float l[NE];
#pragma unroll
        for (int e = 0; e < NE; e++) l[e] = acc[e] + br[e];
        int i0 = 0;
#pragma unroll
        for (int e = 1; e < NE; e++) if (l[e] > l[i0]) i0 = e;
        int i1 = (i0 == 0) ? 1 : 0;
#pragma unroll
        for (int e = 0; e < NE; e++) if (e != i0 && l[e] > l[i1]) i1 = e;
        float w0 = 1.0f / (1.0f + expf(l[i1] - l[i0]));
        g_sel[warp][0] = i0; g_sel[warp][1] = i1;
        g_wts[warp][0] = w0; g_wts[warp][1] = 1.0f - w0;
        atomicAdd(&g_cnt[i0], 1);
        atomicAdd(&g_cnt[i1], 1);
    }
}

__global__ void offsets_kernel() {
    __shared__ int soff[NE + 1];
    if (threadIdx.x == 0) {
        int tot = 0;
        for (int e = 0; e < NE; e++) {
            g_off[e] = tot; soff[e] = tot;
            tot += ((g_cnt[e] + BM - 1) / BM) * BM;
        }
        soff[NE] = tot;
        g_padded_total = tot;
    }
    __syncthreads();
    int tot = soff[NE];
    for (int s = threadIdx.x; s < tot; s += blockDim.x) {
        int e = 0;
        while (s >= soff[e + 1]) e++;
        g_slot_e[s] = e;
        g_slot_tok[s] = -1;
    }
}

__global__ void scatter_kernel() {
    int t = blockIdx.x * blockDim.x + threadIdx.x;
    if (t >= T_TOK) return;
#pragma unroll
    for (int j = 0; j < 2; j++) {
        int e = g_sel[t][j];
        int pos = atomicAdd(&g_cursor[e], 1);
        int s = g_off[e] + pos;
        g_slot_tok[s] = t;
        g_slot_w[s] = g_wts[t][j];
        g_tok_slot[t][j] = s;
    }
}

// gather X rows into slot order -> fp16 (zeros for padding)
__global__ void gather_convert_kernel(const float* __restrict__ x) {
    int idx = blockIdx.x * blockDim.x + threadIdx.x;    // one float4 each
    if (idx >= MAX_SLOTS * DIM / 4) return;
    int slot = idx >> 8;
    int c4 = (idx & 255) << 2;
    int tok = g_slot_tok[slot];
    float4 v = (tok >= 0) ? *(const float4*)(x + (size_t)tok * DIM + c4)
                          : make_float4(0.f, 0.f, 0.f, 0.f);
    __half2 h01 = __floats2half2_rn(v.x, v.y);
    __half2 h23 = __floats2half2_rn(v.z, v.w);
    size_t o = (size_t)slot * DIM + c4;
    *(__half2*)(g_Xf + o)     = h01;
    *(__half2*)(g_Xf + o + 2) = h23;
}

__global__ void convert_f16_kernel(const float* __restrict__ src,
                                   __half* __restrict__ dst, size_t n4) {
    size_t idx = blockIdx.x * (size_t)blockDim.x + threadIdx.x;
    size_t stride = (size_t)gridDim.x * blockDim.x;
    for (size_t i = idx; i < n4; i += stride) {
        float4 v = *(const float4*)(src + i * 4);
        *(__half2*)(dst + i * 4)     = __floats2half2_rn(v.x, v.y);
        *(__half2*)(dst + i * 4 + 2) = __floats2half2_rn(v.z, v.w);
    }
}

// ---------------- HMMA GEMM: C[128x128] = A[m,k] * B[k,n], fp16 in / fp32 acc ----------------
// MODE 0: +b1, exact GELU, -> g_Hf (fp16).   MODE 1: +b2 -> g_Y (fp32).
template<int KD, int NSZ, int MODE>
__global__ __launch_bounds__(256) void gemm_mma_kernel(const __half* __restrict__ A,
                                                       const __half* __restrict__ Bw,
                                                       const float* __restrict__ bias) {
    __shared__ __align__(16) __half As[2][128 * 40];   // row stride 40 halfs = 80B
    __shared__ __align__(16) __half Bs[2][32 * 136];   // row stride 136 halfs = 272B

    const int m0 = blockIdx.x * BM;
    if (m0 >= g_padded_total) return;
    const int n0 = blockIdx.y * BN;
    const int e  = g_slot_e[m0];
    const __half* B = Bw + (size_t)e * KD * NSZ;

    const int tid = threadIdx.x, wid = tid >> 5, lane = tid & 31;
    const int wm = wid >> 1, wn = wid & 1;
    const uint32_t asb = smem_u32(As), bsb = smem_u32(Bs);
    constexpr int NT = KD / 32;

    // per-thread load coords
    const int ar = tid >> 2,        akc = tid & 3;          // A: 2 chunks (tid, tid+256)
    const int ar2 = (tid + 256) >> 2, akc2 = (tid + 256) & 3;
    const int br_ = tid >> 4,       bnc = tid & 15;
    const int br2 = (tid + 256) >> 4, bnc2 = (tid + 256) & 15;

    float acc[2][8][4];
#pragma unroll
    for (int i = 0; i < 2; i++)
#pragma unroll
        for (int j = 0; j < 8; j++)
#pragma unroll
            for (int q = 0; q < 4; q++) acc[i][j][q] = 0.0f;

#define LOAD_STAGE(KT, BUF) do {                                                     \
    uint32_t ab = asb + (BUF) * 10240;                                               \
    uint32_t bb = bsb + (BUF) * 8704;                                                \
    cp16(ab + ar  * 80 + akc  * 16, A + (size_t)(m0 + ar ) * KD + (KT) * 32 + akc  * 8); \
    cp16(ab + ar2 * 80 + akc2 * 16, A + (size_t)(m0 + ar2) * KD + (KT) * 32 + akc2 * 8); \
    cp16(bb + br_ * 272 + bnc  * 16, B + (size_t)((KT) * 32 + br_) * NSZ + n0 + bnc  * 8); \
    cp16(bb + br2 * 272 + bnc2 * 16, B + (size_t)((KT) * 32 + br2) * NSZ + n0 + bnc2 * 8); \
    asm volatile("cp.async.commit_group;" ::: "memory");                             \
} while (0)

    LOAD_STAGE(0, 0);

    // ldmatrix base offsets (constant per thread)
    const uint32_t a_row_off = (uint32_t)((wm * 32 + (lane & 15)) * 80 + (lane >> 4) * 16);
    const uint32_t b_off = (uint32_t)(((lane & 7) + ((lane >> 3) & 1) * 8) * 272
                                      + (wn * 64 + (lane >> 4) * 8) * 2);

    for (int kt = 0; kt < NT; kt++) {
        if (kt + 1 < NT) {
            LOAD_STAGE(kt + 1, (kt + 1) & 1);
            asm volatile("cp.async.wait_group 1;" ::: "memory");
        } else {
            asm volatile("cp.async.wait_group 0;" ::: "memory");
        }
        __syncthreads();

        uint32_t ab = asb + (kt & 1) * 10240;
        uint32_t bb = bsb + (kt & 1) * 8704;
#pragma unroll
        for (int k16 = 0; k16 < 2; k16++) {
            uint32_t a[2][4];
            ldm_x4(a[0], ab + a_row_off + k16 * 32);
            ldm_x4(a[1], ab + a_row_off + 16 * 80 + k16 * 32);
            uint32_t b[4][4];
#pragma unroll
            for (int p = 0; p < 4; p++)
                ldm_x4_t(b[p], bb + b_off + k16 * 16 * 272 + p * 32);
#pragma unroll
            for (int mt = 0; mt < 2; mt++)
#pragma unroll
                for (int p = 0; p < 4; p++) {
                    mma16816(acc[mt][2 * p],     a[mt], b[p][0], b[p][1]);
                    mma16816(acc[mt][2 * p + 1], a[mt], b[p][2], b[p][3]);
                }
        }
        __syncthreads();
    }
#undef LOAD_STAGE

    // epilogue
    const int group = lane >> 2, tig = lane & 3;
#pragma unroll
    for (int mt = 0; mt < 2; mt++) {
        int r = m0 + wm * 32 + mt * 16 + group;
#pragma unroll
        for (int nt = 0; nt < 8; nt++) {
            int c = n0 + wn * 64 + nt * 8 + tig * 2;
            float b0 = __ldg(bias + (size_t)e * NSZ + c);
            float b1v = __ldg(bias + (size_t)e * NSZ + c + 1);
            float v0 = acc[mt][nt][0] + b0;
            float v1 = acc[mt][nt][1] + b1v;
            float v2 = acc[mt][nt][2] + b0;
            float v3 = acc[mt][nt][3] + b1v;
            if (MODE == 0) {
                v0 = 0.5f * v0 * (1.0f + erff(v0 * 0.70710678118654752f));
                v1 = 0.5f * v1 * (1.0f + erff(v1 * 0.70710678118654752f));
                v2 = 0.5f * v2 * (1.0f + erff(v2 * 0.70710678118654752f));
                v3 = 0.5f * v3 * (1.0f + erff(v3 * 0.70710678118654752f));
                *(__half2*)(g_Hf + (size_t)r * NSZ + c)       = __floats2half2_rn(v0, v1);
                *(__half2*)(g_Hf + (size_t)(r + 8) * NSZ + c) = __floats2half2_rn(v2, v3);
            } else {
                *(float2*)(g_Y + (size_t)r * NSZ + c)       = make_float2(v0, v1);
                *(float2*)(g_Y + (size_t)(r + 8) * NSZ + c) = make_float2(v2, v3);
            }
        }
    }
}

// ---------------- weighted combine ----------------
__global__ void combine_kernel(float* __restrict__ out) {
    int idx = blockIdx.x * blockDim.x + threadIdx.x;
    if (idx >= T_TOK * DIM / 4) return;
    int t = idx >> 8;
    int c = (idx & 255) << 2;
    int s0 = g_tok_slot[t][0], s1 = g_tok_slot[t][1];
    float w0 = g_slot_w[s0], w1 = g_slot_w[s1];
    float4 a = *(const float4*)(g_Y + (size_t)s0 * DIM + c);
    float4 b = *(const float4*)(g_Y + (size_t)s1 * DIM + c);
    float4 o;
    o.x = w0 * a.x + w1 * b.x;
    o.y = w0 * a.y + w1 * b.y;
    o.z = w0 * a.z + w1 * b.z;
    o.w = w0 * a.w + w1 * b.w;
    *(float4*)(out + (size_t)t * DIM + c) = o;
}

// ---------------- host ----------------
extern "C" void kernel_launch(void* const* d_in, const int* in_sizes, int n_in,
                              void* d_out, int out_size) {
    const float* x  = (const float*)d_in[0];
    const float* Wr = (const float*)d_in[1];
    const float* br = (const float*)d_in[2];
    const float* W1 = (const float*)d_in[3];
    const float* b1 = (const float*)d_in[4];
    const float* W2 = (const float*)d_in[5];
    const float* b2 = (const float*)d_in[6];
    float* out = (float*)d_out;

    void* pW1f; cudaGetSymbolAddress(&pW1f, g_W1f);
    void* pW2f; cudaGetSymbolAddress(&pW2f, g_W2f);
    void* pXf;  cudaGetSymbolAddress(&pXf,  g_Xf);
    void* pHf;  cudaGetSymbolAddress(&pHf,  g_Hf);

    init_kernel<<<1, 32>>>();
    route_kernel<<<T_TOK / 4, 128>>>(x, Wr, br);
    offsets_kernel<<<1, 256>>>();
    scatter_kernel<<<T_TOK / 256, 256>>>();
    gather_convert_kernel<<<(MAX_SLOTS * DIM / 4 + 255) / 256, 256>>>(x);

    size_t wn4 = (size_t)NE * DIM * HID / 4;
    convert_f16_kernel<<<4096, 256>>>(W1, (__half*)pW1f, wn4);
    convert_f16_kernel<<<4096, 256>>>(W2, (__half*)pW2f, wn4);

    dim3 g1(MTILES, HID / BN);   // 72 x 32
    gemm_mma_kernel<DIM, HID, 0><<<g1, 256>>>((const __half*)pXf, (const __half*)pW1f, b1);
    dim3 g2(MTILES, DIM / BN);   // 72 x 8
    gemm_mma_kernel<HID, DIM, 1><<<g2, 256>>>((const __half*)pHf, (const __half*)pW2f, b2);

    combine_kernel<<<(T_TOK * DIM / 4 + 255) / 256, 256>>>(out);
}